// round 17
// baseline (speedup 1.0000x reference)
#include <cuda_runtime.h>
#include <cuda_bf16.h>
#include <cstdint>

// AggregationLayer: y[s] = mean over edges e with segment_ids[e]==s of
//                   layer_values[gather_idx[e], :]
// d_in[0]: layer_values f32 [N_SRC*64]
// d_in[1]: gather_idx   i32 [E]
// d_in[2]: segment_ids  i32 [E] (sorted ascending)
// out: f32 [n_seg*64]
//
// Single fused edge-centric kernel. Each block owns a 2048-edge span:
// stages seg ids + gather idx, finds segment starts via transition scan
// (no CSR pre-pass), and runs the proven predicated 8-burst gather for
// every segment starting in its span. Boundary-straddling segments are
// finished with a warp-ballot tail walk over global memory.

#define D 64
#define EPB 2048           // edges per block
#define THREADS 256
#define PER_TH (EPB / THREADS)
#define WARPS (THREADS / 32)
#define FULLM 0xffffffffu

__global__ void __launch_bounds__(THREADS, 8)
agg_fused_kernel(const float* __restrict__ vals,
                 const int*   __restrict__ gidx,
                 const int*   __restrict__ segs,
                 float*       __restrict__ out,
                 int E, int n_seg)
{
    __shared__ int s_seg[EPB];
    __shared__ int s_idx[EPB];
    __shared__ int s_starts[EPB];
    __shared__ int s_wsum[WARPS];
    __shared__ int s_total;
    __shared__ int s_segprev;

    const int tid  = threadIdx.x;
    const int w    = tid >> 5;
    const int lane = tid & 31;
    const int base = blockIdx.x * EPB;
    const int n    = min(EPB, E - base);

    // ---- stage seg ids + gather idx (coalesced, streaming) ----
    for (int i = tid; i < n; i += THREADS) {
        s_seg[i] = __ldcs(segs + base + i);
        s_idx[i] = __ldcs(gidx + base + i);
    }
    if (tid == 0) s_segprev = (base == 0) ? -1 : __ldg(segs + base - 1);
    __syncthreads();

    // ---- transition detection + block scan -> sorted start list ----
    int cnt = 0;
    {
        const int p0 = tid * PER_TH;
        #pragma unroll
        for (int k = 0; k < PER_TH; ++k) {
            const int p = p0 + k;
            if (p < n) {
                const int prev = (p == 0) ? s_segprev : s_seg[p - 1];
                if (s_seg[p] != prev) ++cnt;
            }
        }
    }
    // warp inclusive scan of cnt
    int inc = cnt;
    #pragma unroll
    for (int o = 1; o < 32; o <<= 1) {
        int t = __shfl_up_sync(FULLM, inc, o);
        if (lane >= o) inc += t;
    }
    if (lane == 31) s_wsum[w] = inc;
    __syncthreads();
    if (tid == 0) {
        int acc = 0;
        #pragma unroll
        for (int i = 0; i < WARPS; ++i) { int t = s_wsum[i]; s_wsum[i] = acc; acc += t; }
        s_total = acc;
    }
    __syncthreads();
    {
        int off = s_wsum[w] + inc - cnt;
        const int p0 = tid * PER_TH;
        #pragma unroll
        for (int k = 0; k < PER_TH; ++k) {
            const int p = p0 + k;
            if (p < n) {
                const int prev = (p == 0) ? s_segprev : s_seg[p - 1];
                if (s_seg[p] != prev) s_starts[off++] = p;
            }
        }
    }
    __syncthreads();

    const int S = s_total;
    const float2* __restrict__ vals2 = reinterpret_cast<const float2*>(vals);
    float2*       __restrict__ out2  = reinterpret_cast<float2*>(out);

    // ---- warp-per-segment processing ----
    for (int q = w; q < S; q += WARPS) {
        const int p0   = s_starts[q];
        const int sid  = s_seg[p0];
        const bool lastq = (q == S - 1);
        const int p1   = lastq ? n : s_starts[q + 1];

        float ax = 0.f, ay = 0.f;
        int scount = p1 - p0;

        // staged edges: predicated full-width 8-bursts (proven hot loop)
        for (int j = p0; j < p1; j += 8) {
            #pragma unroll
            for (int k = 0; k < 8; ++k) {
                const int  jj = j + k;
                const bool ok = (jj < p1);
                const int  r  = s_idx[ok ? jj : p0];
                const float w8 = ok ? 1.0f : 0.0f;
                float2 v = __ldg(vals2 + (size_t)r * (D/2) + lane);
                ax = fmaf(w8, v.x, ax);
                ay = fmaf(w8, v.y, ay);
            }
        }

        // next segment id (for empty-row fill); default: trailing fill to n_seg
        int next_id = n_seg;

        if (lastq && base + n < E) {
            // tail walk: segment may continue into subsequent blocks
            int e = base + n;
            while (e < E) {
                int v = (e + lane < E) ? __ldg(segs + e + lane) : -1;
                unsigned m = __ballot_sync(FULLM, v == sid);
                int c = (m == FULLM) ? 32 : (__ffs(~m) - 1);
                for (int j = 0; j < c; j += 8) {
                    #pragma unroll
                    for (int k = 0; k < 8; ++k) {
                        const int  jj = j + k;
                        const bool ok = (jj < c);
                        const int  r  = __ldg(gidx + e + (ok ? jj : 0));
                        const float w8 = ok ? 1.0f : 0.0f;
                        float2 vv = __ldg(vals2 + (size_t)r * (D/2) + lane);
                        ax = fmaf(w8, vv.x, ax);
                        ay = fmaf(w8, vv.y, ay);
                    }
                }
                scount += c;
                e += c;
                if (c < 32) {
                    int nv = __shfl_sync(FULLM, v, c);
                    next_id = (e < E) ? nv : n_seg;
                    break;
                }
            }
        } else if (!lastq) {
            next_id = s_seg[s_starts[q + 1]];
        }
        // else: lastq && base+n >= E -> next_id stays n_seg (trailing fill)

        // write mean row
        const float inv = 1.0f / (float)max(scount, 1);
        float2 res;
        res.x = ax * inv;
        res.y = ay * inv;
        __stcs(out2 + (size_t)sid * (D/2) + lane, res);

        // zero-fill empty segments (sid, next_id)
        for (int z = sid + 1; z < next_id; ++z) {
            float2 zz; zz.x = 0.f; zz.y = 0.f;
            __stcs(out2 + (size_t)z * (D/2) + lane, zz);
        }
        // leading empties before the globally-first segment
        if (base == 0 && q == 0) {
            for (int z = 0; z < sid; ++z) {
                float2 zz; zz.x = 0.f; zz.y = 0.f;
                __stcs(out2 + (size_t)z * (D/2) + lane, zz);
            }
        }
    }
}

extern "C" void kernel_launch(void* const* d_in, const int* in_sizes, int n_in,
                              void* d_out, int out_size)
{
    const float* vals = (const float*)d_in[0];
    const int*   gidx = (const int*)d_in[1];
    const int*   segs = (const int*)d_in[2];
    float*       out  = (float*)d_out;

    const int E     = in_sizes[1];
    const int n_seg = out_size / D;

    const int blocks = (E + EPB - 1) / EPB;
    agg_fused_kernel<<<blocks, THREADS>>>(vals, gidx, segs, out, E, n_seg);
}